// round 1
// baseline (speedup 1.0000x reference)
#include <cuda_runtime.h>
#include <cstdint>
#include <cstdio>

// Problem constants (fixed by the dataset)
#define NNODES 100000
#define NEDGES 640000
#define HID    128
#define NHEADS 8
#define HDIM   16

// ---------------- scratch (device globals; no runtime allocation) ----------
__device__ float g_Q[(size_t)NNODES * HID];
__device__ float g_K[(size_t)NNODES * HID];
__device__ float g_V[(size_t)NNODES * HID];
__device__ float g_AGG[(size_t)NNODES * HID];
__device__ int   g_deg[NNODES];
__device__ int   g_rowptr[NNODES + 1];
__device__ int   g_cursor[NNODES];
__device__ int   g_perm[NEDGES];

// ---------------- helpers ---------------------------------------------------
__device__ __forceinline__ uint32_t f2tf32(float x) {
    uint32_t r;
    asm("cvt.rna.tf32.f32 %0, %1;" : "=r"(r) : "f"(x));
    return r;
}

__device__ __forceinline__ void mma_tf32(float& c0, float& c1, float& c2, float& c3,
                                         uint32_t a0, uint32_t a1, uint32_t a2, uint32_t a3,
                                         uint32_t b0, uint32_t b1) {
    asm volatile(
        "mma.sync.aligned.m16n8k8.row.col.f32.tf32.tf32.f32 "
        "{%0,%1,%2,%3}, {%4,%5,%6,%7}, {%8,%9}, {%0,%1,%2,%3};"
        : "+f"(c0), "+f"(c1), "+f"(c2), "+f"(c3)
        : "r"(a0), "r"(a1), "r"(a2), "r"(a3), "r"(b0), "r"(b1));
}

// ---------------- GEMM: Y[M,128] = X[M,128] @ W^T + bias --------------------
// W is [128,128] row-major, W[n][k]. Block: 256 thr (8 warps), 128 rows/block.
// tf32 mma m16n8k8, full K=128 in shared memory (padded stride 132 -> conflict free).
#define SLD 132
#define GEMM_SMEM_BYTES (2 * 128 * SLD * 4)

extern "C" __global__ void __launch_bounds__(256, 1)
gemm128_tf32(const float* __restrict__ X, const float* __restrict__ W,
             const float* __restrict__ bias, float* __restrict__ Y, int M) {
    extern __shared__ uint32_t smem[];
    uint32_t* sX = smem;
    uint32_t* sW = smem + 128 * SLD;

    const int tid = threadIdx.x;
    const int m0 = blockIdx.x * 128;

    // Stage W (tf32-converted)
    #pragma unroll 4
    for (int i = tid; i < 4096; i += 256) {
        int r = i >> 5, c = (i & 31) * 4;
        float4 w4 = *(const float4*)(W + (size_t)r * HID + c);
        uint32_t* p = sW + r * SLD + c;
        p[0] = f2tf32(w4.x); p[1] = f2tf32(w4.y); p[2] = f2tf32(w4.z); p[3] = f2tf32(w4.w);
    }
    // Stage X tile (tf32-converted, zero pad past M)
    #pragma unroll 4
    for (int i = tid; i < 4096; i += 256) {
        int r = i >> 5, c = (i & 31) * 4;
        int gr = m0 + r;
        float4 x4 = make_float4(0.f, 0.f, 0.f, 0.f);
        if (gr < M) x4 = *(const float4*)(X + (size_t)gr * HID + c);
        uint32_t* p = sX + r * SLD + c;
        p[0] = f2tf32(x4.x); p[1] = f2tf32(x4.y); p[2] = f2tf32(x4.z); p[3] = f2tf32(x4.w);
    }
    __syncthreads();

    const int w = tid >> 5, lane = tid & 31;
    const int g = lane >> 2, tig = lane & 3;

    float c[16][4];
    #pragma unroll
    for (int nt = 0; nt < 16; nt++) { c[nt][0] = c[nt][1] = c[nt][2] = c[nt][3] = 0.f; }

    const uint32_t* ax0 = sX + (w * 16 + g) * SLD;
    const uint32_t* ax1 = sX + (w * 16 + g + 8) * SLD;

    #pragma unroll
    for (int kt = 0; kt < 16; kt++) {
        const int k0 = kt * 8;
        uint32_t a0 = ax0[k0 + tig];
        uint32_t a1 = ax1[k0 + tig];
        uint32_t a2 = ax0[k0 + tig + 4];
        uint32_t a3 = ax1[k0 + tig + 4];
        #pragma unroll
        for (int nt = 0; nt < 16; nt++) {
            const uint32_t* bw = sW + (nt * 8 + g) * SLD + k0;
            uint32_t b0 = bw[tig];
            uint32_t b1 = bw[tig + 4];
            mma_tf32(c[nt][0], c[nt][1], c[nt][2], c[nt][3], a0, a1, a2, a3, b0, b1);
        }
    }

    const int row0 = m0 + w * 16 + g;
    const int row1 = row0 + 8;
    #pragma unroll
    for (int nt = 0; nt < 16; nt++) {
        int col = nt * 8 + tig * 2;
        float b0 = __ldg(bias + col);
        float b1 = __ldg(bias + col + 1);
        if (row0 < M) {
            float2 o = make_float2(c[nt][0] + b0, c[nt][1] + b1);
            *(float2*)(Y + (size_t)row0 * HID + col) = o;
        }
        if (row1 < M) {
            float2 o = make_float2(c[nt][2] + b0, c[nt][3] + b1);
            *(float2*)(Y + (size_t)row1 * HID + col) = o;
        }
    }
}

// ---------------- CSR build -------------------------------------------------
extern "C" __global__ void zero_deg_kernel(int n) {
    int i = blockIdx.x * blockDim.x + threadIdx.x;
    if (i < n) g_deg[i] = 0;
}

extern "C" __global__ void hist_kernel(const int* __restrict__ s_idx, int E) {
    int e = blockIdx.x * blockDim.x + threadIdx.x;
    if (e < E) atomicAdd(&g_deg[s_idx[e]], 1);
}

extern "C" __global__ void __launch_bounds__(1024, 1) scan_kernel(int n) {
    __shared__ int wsum[32];
    __shared__ int s_base;
    const int tid = threadIdx.x, lane = tid & 31, wid = tid >> 5;
    if (tid == 0) s_base = 0;
    __syncthreads();

    for (int chunk = 0; chunk < n; chunk += 1024) {
        int i = chunk + tid;
        int v = (i < n) ? g_deg[i] : 0;
        int x = v;
        #pragma unroll
        for (int o = 1; o < 32; o <<= 1) {
            int y = __shfl_up_sync(0xffffffffu, x, o);
            if (lane >= o) x += y;
        }
        if (lane == 31) wsum[wid] = x;
        __syncthreads();
        if (wid == 0) {
            int s = wsum[lane];
            #pragma unroll
            for (int o = 1; o < 32; o <<= 1) {
                int y = __shfl_up_sync(0xffffffffu, s, o);
                if (lane >= o) s += y;
            }
            wsum[lane] = s;
        }
        __syncthreads();
        int excl = x - v + (wid > 0 ? wsum[wid - 1] : 0);
        int base = s_base;
        int total = wsum[31];
        if (i < n) {
            int off = base + excl;
            g_rowptr[i] = off;
            g_cursor[i] = off;
        }
        __syncthreads();
        if (tid == 0) s_base = base + total;
        __syncthreads();
    }
    if (tid == 0) g_rowptr[n] = s_base;
}

extern "C" __global__ void scatter_kernel(const int* __restrict__ s_idx, int E) {
    int e = blockIdx.x * blockDim.x + threadIdx.x;
    if (e < E) {
        int s = s_idx[e];
        int pos = atomicAdd(&g_cursor[s], 1);
        g_perm[pos] = e;
    }
}

// ---------------- per-node attention (one warp per node, atomic-free) -------
// For node n: for each incident edge e (src==n): score_h = <Q[n,h,:],K[d,h,:]>/4,
// p = exp(score), acc += p*V[d], z += p. Output agg[n] = acc / z (0 if no edges).
extern "C" __global__ void __launch_bounds__(256) node_attn_kernel(
    const int* __restrict__ d_idx, int n_nodes) {
    int node = (int)((blockIdx.x * (unsigned)blockDim.x + threadIdx.x) >> 5);
    int lane = threadIdx.x & 31;
    if (node >= n_nodes) return;

    int beg = g_rowptr[node];
    int end = g_rowptr[node + 1];

    float4 q4 = *(const float4*)(g_Q + (size_t)node * HID + lane * 4);
    float4 acc = make_float4(0.f, 0.f, 0.f, 0.f);
    float zacc = 0.f;

    for (int i = beg; i < end; ++i) {
        int e = g_perm[i];
        int d = __ldg(d_idx + e);
        const float4 k4 = __ldg((const float4*)(g_K + (size_t)d * HID) + lane);
        float part = q4.x * k4.x + q4.y * k4.y + q4.z * k4.z + q4.w * k4.w;
        part += __shfl_xor_sync(0xffffffffu, part, 1);
        part += __shfl_xor_sync(0xffffffffu, part, 2);
        float p = __expf(part * 0.25f);  // scaling = HEAD_DIM^-0.5 = 0.25
        const float4 v4 = __ldg((const float4*)(g_V + (size_t)d * HID) + lane);
        acc.x += p * v4.x; acc.y += p * v4.y; acc.z += p * v4.z; acc.w += p * v4.w;
        zacc += p;
    }

    float inv = (zacc > 0.f) ? (1.f / zacc) : 0.f;
    float4 o = make_float4(acc.x * inv, acc.y * inv, acc.z * inv, acc.w * inv);
    *(float4*)(g_AGG + (size_t)node * HID + lane * 4) = o;
}

// ---------------- launch ----------------------------------------------------
extern "C" void kernel_launch(void* const* d_in, const int* in_sizes, int n_in,
                              void* d_out, int out_size) {
    const float* src_x = (const float*)d_in[0];
    const float* dst_x = (const float*)d_in[1];
    const float* Wq = (const float*)d_in[2];
    const float* bq = (const float*)d_in[3];
    const float* Wk = (const float*)d_in[4];
    const float* bk = (const float*)d_in[5];
    const float* Wv = (const float*)d_in[6];
    const float* bv = (const float*)d_in[7];
    const float* Wo = (const float*)d_in[8];
    const float* bo = (const float*)d_in[9];
    const int* ei = (const int*)d_in[10];

    const int N = in_sizes[0] / HID;      // 100000
    const int E = in_sizes[10] / 2;       // 640000
    const int* s_idx = ei;
    const int* d_idx = ei + E;

    float *Qp, *Kp, *Vp, *Ap;
    cudaGetSymbolAddress((void**)&Qp, g_Q);
    cudaGetSymbolAddress((void**)&Kp, g_K);
    cudaGetSymbolAddress((void**)&Vp, g_V);
    cudaGetSymbolAddress((void**)&Ap, g_AGG);

    cudaFuncSetAttribute(gemm128_tf32, cudaFuncAttributeMaxDynamicSharedMemorySize,
                         GEMM_SMEM_BYTES);

    const int gemm_blocks = (N + 127) / 128;

    // Projections
    gemm128_tf32<<<gemm_blocks, 256, GEMM_SMEM_BYTES>>>(src_x, Wq, bq, Qp, N);
    gemm128_tf32<<<gemm_blocks, 256, GEMM_SMEM_BYTES>>>(dst_x, Wk, bk, Kp, N);
    gemm128_tf32<<<gemm_blocks, 256, GEMM_SMEM_BYTES>>>(dst_x, Wv, bv, Vp, N);

    // CSR build
    zero_deg_kernel<<<(N + 255) / 256, 256>>>(N);
    hist_kernel<<<(E + 255) / 256, 256>>>(s_idx, E);
    scan_kernel<<<1, 1024>>>(N);
    scatter_kernel<<<(E + 255) / 256, 256>>>(s_idx, E);

    // Fused score + softmax + aggregate (one warp per node)
    node_attn_kernel<<<(N + 7) / 8, 256>>>(d_idx, N);

    // Output projection
    gemm128_tf32<<<gemm_blocks, 256, GEMM_SMEM_BYTES>>>(Ap, Wo, bo, (float*)d_out, N);
}

// round 2
// speedup vs baseline: 1.5137x; 1.5137x over previous
#include <cuda_runtime.h>
#include <cstdint>

#define NNODES 100000
#define NEDGES 640000
#define HID    128

// ---------------- scratch (device globals) ----------------------------------
__device__ float g_Q[(size_t)NNODES * HID];
__device__ float g_K[(size_t)NNODES * HID];
__device__ float g_V[(size_t)NNODES * HID];
__device__ float g_AGG[(size_t)NNODES * HID];
__device__ int   g_deg[NNODES];
__device__ int   g_rowptr[NNODES];
__device__ int   g_cursor[NNODES];
__device__ int   g_perm[NEDGES];
__device__ int   g_total;

// ---------------- helpers ----------------------------------------------------
__device__ __forceinline__ uint32_t f2tf32(float x) {
    uint32_t r;
    asm("cvt.rna.tf32.f32 %0, %1;" : "=r"(r) : "f"(x));
    return r;
}

__device__ __forceinline__ void mma_tf32(float& c0, float& c1, float& c2, float& c3,
                                         uint32_t a0, uint32_t a1, uint32_t a2, uint32_t a3,
                                         uint32_t b0, uint32_t b1) {
    asm volatile(
        "mma.sync.aligned.m16n8k8.row.col.f32.tf32.tf32.f32 "
        "{%0,%1,%2,%3}, {%4,%5,%6,%7}, {%8,%9}, {%0,%1,%2,%3};"
        : "+f"(c0), "+f"(c1), "+f"(c2), "+f"(c3)
        : "r"(a0), "r"(a1), "r"(a2), "r"(a3), "r"(b0), "r"(b1));
}

// ---------------- persistent GEMM ------------------------------------------
// Y[M,128] = X[M,128] @ W^T + b, optionally two W/b/Y pairs sharing X.
// Layout: k-values pair-interleaved so (k, k+4) are adjacent words:
//   pos(k) = (k & ~7) | ((k & 3) << 1) | ((k >> 2) & 1)
// Row stride SLDW = 136 words -> 8-row groups hit disjoint bank octets.
#define SLDW 136
#define TROWS 64   // rows per X tile

// Stage a 128x128 weight matrix (tf32) into smem, interleaved.
__device__ __forceinline__ void stage_w(uint32_t* sW, const float* __restrict__ W, int tid) {
    #pragma unroll
    for (int j = 0; j < 16; j++) {
        int f = j * 256 + tid;
        int r = f >> 5, c4 = f & 31, c = c4 * 4;
        float4 w4 = *(const float4*)(W + r * HID + c);
        int base = r * SLDW + (c & ~7) + (c4 & 1);
        sW[base + 0] = f2tf32(w4.x);
        sW[base + 2] = f2tf32(w4.y);
        sW[base + 4] = f2tf32(w4.z);
        sW[base + 6] = f2tf32(w4.w);
    }
}

__device__ __forceinline__ void load_x_regs(float4 (&xr)[8], const float* __restrict__ X,
                                            int tile, int M, int tid) {
    int rbase = tile * TROWS;
    #pragma unroll
    for (int j = 0; j < 8; j++) {
        int f = j * 256 + tid;
        int r = f >> 5, c4 = f & 31;
        int gr = rbase + r;
        xr[j] = (gr < M) ? *(const float4*)(X + (size_t)gr * HID + c4 * 4)
                         : make_float4(0.f, 0.f, 0.f, 0.f);
    }
}

__device__ __forceinline__ void sts_x(uint32_t* sX, const float4 (&xr)[8], int tid) {
    #pragma unroll
    for (int j = 0; j < 8; j++) {
        int f = j * 256 + tid;
        int r = f >> 5, c4 = f & 31, c = c4 * 4;
        int base = r * SLDW + (c & ~7) + (c4 & 1);
        sX[base + 0] = f2tf32(xr[j].x);
        sX[base + 2] = f2tf32(xr[j].y);
        sX[base + 4] = f2tf32(xr[j].z);
        sX[base + 6] = f2tf32(xr[j].w);
    }
}

// Compute + epilogue for one tile. Warp w: m-tile = w>>1 (16 rows), n-half = w&1.
template<int NM>
__device__ __forceinline__ void tile_compute(
    const uint32_t* sX, const uint32_t* sW0, const uint32_t* sW1,
    const float* __restrict__ b0, const float* __restrict__ b1,
    float* __restrict__ Y0, float* __restrict__ Y1,
    int tile, int M, int tid) {

    const int w = tid >> 5, lane = tid & 31;
    const int g = lane >> 2, tig = lane & 3;
    const int mrow0 = (w >> 1) * 16 + g;
    const int mrow1 = mrow0 + 8;
    const int nbase = (w & 1) * 64;

    float c0[8][4], c1[8][4];
    #pragma unroll
    for (int nt = 0; nt < 8; nt++) {
        c0[nt][0] = c0[nt][1] = c0[nt][2] = c0[nt][3] = 0.f;
        if (NM == 2) { c1[nt][0] = c1[nt][1] = c1[nt][2] = c1[nt][3] = 0.f; }
    }

    const uint32_t* axA = sX + mrow0 * SLDW + tig * 2;
    const uint32_t* axB = sX + mrow1 * SLDW + tig * 2;

    #pragma unroll
    for (int kt = 0; kt < 16; kt++) {
        const int ko = kt * 8;
        uint2 aA = *(const uint2*)(axA + ko);
        uint2 aB = *(const uint2*)(axB + ko);
        #pragma unroll
        for (int nt = 0; nt < 8; nt++) {
            int wrow = (nbase + nt * 8 + g) * SLDW + ko + tig * 2;
            uint2 b = *(const uint2*)(sW0 + wrow);
            mma_tf32(c0[nt][0], c0[nt][1], c0[nt][2], c0[nt][3],
                     aA.x, aB.x, aA.y, aB.y, b.x, b.y);
            if (NM == 2) {
                uint2 b2 = *(const uint2*)(sW1 + wrow);
                mma_tf32(c1[nt][0], c1[nt][1], c1[nt][2], c1[nt][3],
                         aA.x, aB.x, aA.y, aB.y, b2.x, b2.y);
            }
        }
    }

    const int row0 = tile * TROWS + mrow0;
    const int row1 = tile * TROWS + mrow1;
    #pragma unroll
    for (int nt = 0; nt < 8; nt++) {
        int col = nbase + nt * 8 + tig * 2;
        float bb0 = __ldg(b0 + col), bb1 = __ldg(b0 + col + 1);
        if (row0 < M) *(float2*)(Y0 + (size_t)row0 * HID + col) =
            make_float2(c0[nt][0] + bb0, c0[nt][1] + bb1);
        if (row1 < M) *(float2*)(Y0 + (size_t)row1 * HID + col) =
            make_float2(c0[nt][2] + bb0, c0[nt][3] + bb1);
        if (NM == 2) {
            float cb0 = __ldg(b1 + col), cb1 = __ldg(b1 + col + 1);
            if (row0 < M) *(float2*)(Y1 + (size_t)row0 * HID + col) =
                make_float2(c1[nt][0] + cb0, c1[nt][1] + cb1);
            if (row1 < M) *(float2*)(Y1 + (size_t)row1 * HID + col) =
                make_float2(c1[nt][2] + cb0, c1[nt][3] + cb1);
        }
    }
}

template<int NM>
__device__ __forceinline__ void gemm_body(
    const float* __restrict__ X,
    const float* __restrict__ W0, const float* __restrict__ b0, float* __restrict__ Y0,
    const float* __restrict__ W1, const float* __restrict__ b1, float* __restrict__ Y1,
    int M) {
    extern __shared__ uint32_t smem[];
    uint32_t* sW0 = smem;
    uint32_t* sW1 = (NM == 2) ? smem + 128 * SLDW : smem;
    uint32_t* sX  = smem + NM * 128 * SLDW;

    const int tid = threadIdx.x;
    const int ntiles = (M + TROWS - 1) / TROWS;

    stage_w(sW0, W0, tid);
    if (NM == 2) stage_w(sW1, W1, tid);

    int t = blockIdx.x;
    if (t >= ntiles) return;

    float4 xr[8];
    load_x_regs(xr, X, t, M, tid);
    sts_x(sX, xr, tid);
    __syncthreads();

    while (true) {
        int tn = t + gridDim.x;
        if (tn < ntiles) load_x_regs(xr, X, tn, M, tid);   // overlaps with compute
        tile_compute<NM>(sX, sW0, sW1, b0, b1, Y0, Y1, t, M, tid);
        if (tn >= ntiles) break;
        __syncthreads();
        sts_x(sX, xr, tid);
        __syncthreads();
        t = tn;
    }
}

extern "C" __global__ void __launch_bounds__(256, 2)
gemm_p1(const float* __restrict__ X, const float* __restrict__ W0,
        const float* __restrict__ b0, float* __restrict__ Y0, int M) {
    gemm_body<1>(X, W0, b0, Y0, nullptr, nullptr, nullptr, M);
}

extern "C" __global__ void __launch_bounds__(256, 1)
gemm_p2(const float* __restrict__ X,
        const float* __restrict__ W0, const float* __restrict__ b0, float* __restrict__ Y0,
        const float* __restrict__ W1, const float* __restrict__ b1, float* __restrict__ Y1,
        int M) {
    gemm_body<2>(X, W0, b0, Y0, W1, b1, Y1, M);
}

#define SMEM_P1 ((1 * 128 + TROWS) * SLDW * 4)
#define SMEM_P2 ((2 * 128 + TROWS) * SLDW * 4)

// ---------------- CSR build --------------------------------------------------
extern "C" __global__ void hist_kernel(const int* __restrict__ s_idx, int E) {
    int e = blockIdx.x * blockDim.x + threadIdx.x;
    if (e == 0) g_total = 0;
    if (e < E) atomicAdd(&g_deg[s_idx[e]], 1);
}

// Block-level exclusive scan + atomic base allocation (ranges disjoint, unordered).
extern "C" __global__ void __launch_bounds__(1024) alloc_kernel(int n) {
    __shared__ int wsum[32];
    __shared__ int sbase;
    const int tid = threadIdx.x, lane = tid & 31, wid = tid >> 5;
    int i = blockIdx.x * 1024 + tid;
    int v = (i < n) ? g_deg[i] : 0;
    int x = v;
    #pragma unroll
    for (int o = 1; o < 32; o <<= 1) {
        int y = __shfl_up_sync(0xffffffffu, x, o);
        if (lane >= o) x += y;
    }
    if (lane == 31) wsum[wid] = x;
    __syncthreads();
    if (wid == 0) {
        int s = wsum[lane];
        #pragma unroll
        for (int o = 1; o < 32; o <<= 1) {
            int y = __shfl_up_sync(0xffffffffu, s, o);
            if (lane >= o) s += y;
        }
        wsum[lane] = s;
    }
    __syncthreads();
    if (tid == 0) sbase = atomicAdd(&g_total, wsum[31]);
    __syncthreads();
    int excl = x - v + (wid > 0 ? wsum[wid - 1] : 0);
    if (i < n) {
        int off = sbase + excl;
        g_rowptr[i] = off;
        g_cursor[i] = off;
    }
}

// Store destination node id directly (removes one indirection in attention).
extern "C" __global__ void scatter_kernel(const int* __restrict__ s_idx,
                                          const int* __restrict__ d_idx, int E) {
    int e = blockIdx.x * blockDim.x + threadIdx.x;
    if (e < E) {
        int pos = atomicAdd(&g_cursor[s_idx[e]], 1);
        g_perm[pos] = d_idx[e];
    }
}

// ---------------- per-node attention (half-warp per edge) --------------------
extern "C" __global__ void __launch_bounds__(256) node_attn_kernel(int n_nodes) {
    int node = (int)((blockIdx.x * 256u + threadIdx.x) >> 5);
    if (node >= n_nodes) return;
    const int lane = threadIdx.x & 31;
    const int h = lane & 15;          // 8-float column chunk owner
    const int side = lane >> 4;       // which of 2 parallel edges

    const int beg = g_rowptr[node];
    const int dg  = g_deg[node];
    const int end = beg + dg;

    const float* qp = g_Q + (size_t)node * HID + h * 8;
    const float4 qa = *(const float4*)qp;
    const float4 qb = *(const float4*)(qp + 4);

    float4 aA = make_float4(0.f, 0.f, 0.f, 0.f);
    float4 aB = make_float4(0.f, 0.f, 0.f, 0.f);
    float z = 0.f;

    const int iters = (dg + 1) >> 1;
    int idx = beg + side;
    int d = (idx < end) ? g_perm[idx] : 0;
    for (int it = 0; it < iters; ++it) {
        bool val = idx < end;
        int idxn = idx + 2;
        int dn = (idxn < end) ? g_perm[idxn] : 0;    // prefetch next

        const float* kp = g_K + (size_t)d * HID + h * 8;
        const float* vp = g_V + (size_t)d * HID + h * 8;
        float4 k4a = *(const float4*)kp;
        float4 k4b = *(const float4*)(kp + 4);
        float4 v4a = *(const float4*)vp;             // issued before reduction
        float4 v4b = *(const float4*)(vp + 4);

        float part = qa.x * k4a.x + qa.y * k4a.y + qa.z * k4a.z + qa.w * k4a.w
                   + qb.x * k4b.x + qb.y * k4b.y + qb.z * k4b.z + qb.w * k4b.w;
        part += __shfl_xor_sync(0xffffffffu, part, 1);   // head = pair of lanes
        float p = val ? __expf(part * 0.25f) : 0.f;       // 1/sqrt(16)
        z += p;
        aA.x += p * v4a.x; aA.y += p * v4a.y; aA.z += p * v4a.z; aA.w += p * v4a.w;
        aB.x += p * v4b.x; aB.y += p * v4b.y; aB.z += p * v4b.z; aB.w += p * v4b.w;

        idx = idxn; d = dn;
    }

    // combine the two half-warps
    z += __shfl_xor_sync(0xffffffffu, z, 16);
    aA.x += __shfl_xor_sync(0xffffffffu, aA.x, 16);
    aA.y += __shfl_xor_sync(0xffffffffu, aA.y, 16);
    aA.z += __shfl_xor_sync(0xffffffffu, aA.z, 16);
    aA.w += __shfl_xor_sync(0xffffffffu, aA.w, 16);
    aB.x += __shfl_xor_sync(0xffffffffu, aB.x, 16);
    aB.y += __shfl_xor_sync(0xffffffffu, aB.y, 16);
    aB.z += __shfl_xor_sync(0xffffffffu, aB.z, 16);
    aB.w += __shfl_xor_sync(0xffffffffu, aB.w, 16);

    if (lane < 16) {
        float inv = (z > 0.f) ? (1.f / z) : 0.f;
        float* op = g_AGG + (size_t)node * HID + h * 8;
        *(float4*)op = make_float4(aA.x * inv, aA.y * inv, aA.z * inv, aA.w * inv);
        *(float4*)(op + 4) = make_float4(aB.x * inv, aB.y * inv, aB.z * inv, aB.w * inv);
    }
}

// ---------------- launch -----------------------------------------------------
extern "C" void kernel_launch(void* const* d_in, const int* in_sizes, int n_in,
                              void* d_out, int out_size) {
    const float* src_x = (const float*)d_in[0];
    const float* dst_x = (const float*)d_in[1];
    const float* Wq = (const float*)d_in[2];
    const float* bq = (const float*)d_in[3];
    const float* Wk = (const float*)d_in[4];
    const float* bk = (const float*)d_in[5];
    const float* Wv = (const float*)d_in[6];
    const float* bv = (const float*)d_in[7];
    const float* Wo = (const float*)d_in[8];
    const float* bo = (const float*)d_in[9];
    const int* ei = (const int*)d_in[10];

    const int N = in_sizes[0] / HID;
    const int E = in_sizes[10] / 2;
    const int* s_idx = ei;
    const int* d_idx = ei + E;

    float *Qp, *Kp, *Vp, *Ap;
    cudaGetSymbolAddress((void**)&Qp, g_Q);
    cudaGetSymbolAddress((void**)&Kp, g_K);
    cudaGetSymbolAddress((void**)&Vp, g_V);
    cudaGetSymbolAddress((void**)&Ap, g_AGG);
    void* degp;
    cudaGetSymbolAddress(&degp, g_deg);

    int sm_count = 148;
    cudaDeviceGetAttribute(&sm_count, cudaDevAttrMultiProcessorCount, 0);

    cudaFuncSetAttribute(gemm_p1, cudaFuncAttributeMaxDynamicSharedMemorySize, SMEM_P1);
    cudaFuncSetAttribute(gemm_p2, cudaFuncAttributeMaxDynamicSharedMemorySize, SMEM_P2);

    // CSR build
    cudaMemsetAsync(degp, 0, (size_t)N * sizeof(int));
    hist_kernel<<<(E + 255) / 256, 256>>>(s_idx, E);              // k0
    alloc_kernel<<<(N + 1023) / 1024, 1024>>>(N);                 // k1
    scatter_kernel<<<(E + 255) / 256, 256>>>(s_idx, d_idx, E);    // k2

    // Projections (fused KV lands 4th -> profiled next round)
    gemm_p2<<<sm_count, 256, SMEM_P2>>>(dst_x, Wk, bk, Kp, Wv, bv, Vp, N);   // k3
    gemm_p1<<<2 * sm_count, 256, SMEM_P1>>>(src_x, Wq, bq, Qp, N);           // k4

    // Fused score + softmax + aggregate
    node_attn_kernel<<<(N + 7) / 8, 256>>>(N);                    // k5

    // Output projection
    gemm_p1<<<2 * sm_count, 256, SMEM_P1>>>(Ap, Wo, bo, (float*)d_out, N);   // k6
}